// round 6
// baseline (speedup 1.0000x reference)
#include <cuda_runtime.h>
#include <cuda_fp16.h>

#define BB 2
#define CC 8
#define HH 512
#define WW 1024
#define OC 8
#define KY 3
#define KX 3
#define KK (KY*KX)
#define HW (HH*WW)

// fp16 transposed input: [b][pix] -> 8 channels packed in 16 bytes.
__device__ __align__(16) uint4 g_h[(size_t)BB * HW];

__global__ __launch_bounds__(256) void transpose_h(const float* __restrict__ x) {
    int idx = blockIdx.x * 256 + threadIdx.x;
    if (idx >= BB * HW) return;
    int b = idx >> 19;
    int hw = idx & (HW - 1);
    const float* xp = x + (size_t)b * CC * HW + hw;
    __half2 p0 = __floats2half2_rn(xp[0 * HW], xp[1 * HW]);
    __half2 p1 = __floats2half2_rn(xp[2 * HW], xp[3 * HW]);
    __half2 p2 = __floats2half2_rn(xp[4 * HW], xp[5 * HW]);
    __half2 p3 = __floats2half2_rn(xp[6 * HW], xp[7 * HW]);
    uint4 q;
    q.x = *reinterpret_cast<unsigned*>(&p0);
    q.y = *reinterpret_cast<unsigned*>(&p1);
    q.z = *reinterpret_cast<unsigned*>(&p2);
    q.w = *reinterpret_cast<unsigned*>(&p3);
    g_h[idx] = q;
}

// atan2 with single fast division + Cephes poly. ~1e-7 rad error.
__device__ __forceinline__ float fast_atan2f(float y, float x) {
    float ay = fabsf(y), ax = fabsf(x);
    float n = fminf(ay, ax), d = fmaxf(ay, ax);
    bool big = n > 0.4142135624f * d;
    float num = big ? (n - d) : n;
    float den = big ? (n + d) : d;
    float t = __fdividef(num, den);
    float z = t * t;
    float p = fmaf(fmaf(fmaf(8.05374449538e-2f, z, -1.38776856032e-1f), z,
                        1.99777106478e-1f), z, -3.33329491539e-1f);
    float r = fmaf(p * z, t, t);
    if (big) r += 0.78539816339744831f;
    if (ay > ax) r = 1.57079632679489662f - r;
    if (x < 0.0f) r = 3.14159265358979323f - r;
    return copysignf(r, y);
}

__device__ __forceinline__ unsigned long long dup_f32x2(float f) {
    unsigned long long r;
    asm("mov.b64 %0, {%1, %1};" : "=l"(r) : "f"(f));
    return r;
}

__device__ __forceinline__ void ffma2(unsigned long long& acc,
                                      unsigned long long a, unsigned long long b) {
    asm("fma.rn.f32x2 %0, %1, %2, %0;" : "+l"(acc) : "l"(a), "l"(b));
}

// y-combine two row pixels (8 fp16 ch), shuffle-in x-neighbor, x-combine,
// producing 8 fp32 channel values for this lane's output pixel.
__device__ __forceinline__ void sample8(uint4 P0, uint4 P1, uint4 E0, uint4 E1,
                                        __half2 wy0, __half2 wy1,
                                        __half2 wx0, __half2 wx1,
                                        int lane, float* v) {
    const __half2* p0 = reinterpret_cast<const __half2*>(&P0);
    const __half2* p1 = reinterpret_cast<const __half2*>(&P1);
    const __half2* e0 = reinterpret_cast<const __half2*>(&E0);
    const __half2* e1 = reinterpret_cast<const __half2*>(&E1);
    __half2 M[4], Me[4];
#pragma unroll
    for (int j = 0; j < 4; j++) {
        M[j]  = __hfma2(p1[j], wy1, __hmul2(p0[j], wy0));
        Me[j] = __hfma2(e1[j], wy1, __hmul2(e0[j], wy0));
    }
#pragma unroll
    for (int j = 0; j < 4; j++) {
        unsigned mi = *reinterpret_cast<unsigned*>(&M[j]);
        unsigned ms = __shfl_down_sync(0xffffffffu, mi, 1);
        __half2 Mn = (lane == 31) ? Me[j] : *reinterpret_cast<__half2*>(&ms);
        __half2 V = __hfma2(Mn, wx1, __hmul2(M[j], wx0));
        float2 f = __half22float2(V);
        v[2 * j]     = f.x;
        v[2 * j + 1] = f.y;
    }
}

__global__ __launch_bounds__(256, 4) void sconv_kernel(const float* __restrict__ wgt,
                                                       const float* __restrict__ bias,
                                                       float* __restrict__ out) {
    constexpr float PI_F = 3.14159265358979323846f;
    __shared__ __align__(16) float ws[KK * CC * OC]; // [k][c][o]
    __shared__ __align__(16) float4 s_map[8][KK];    // {dgx, fy, iy0*W, iy1*W}
    __shared__ float sb[OC];

    int tid = threadIdx.y * 32 + threadIdx.x;
    for (int i = tid; i < KK * CC * OC; i += 256) {
        int k = i >> 6;
        int c = (i >> 3) & 7;
        int o = i & 7;
        ws[i] = wgt[(o * CC + c) * KK + k];
    }
    if (tid < OC) sb[tid] = bias[tid];

    // Per-(h,k) geometry: gx = w + dgx(h,k); gy depends on (h,k) only.
    if (tid < 8 * KK) {
        int ty = tid / KK;
        int k = tid - ty * KK;
        int h = blockIdx.y * 8 + ty;
        const float scale = PI_F / (float)HH;
        const float gx_scale = (float)WW / (2.0f * PI_F);
        const float gy_scale = (float)HH / PI_F;
        float po = PI_F * ((float)(2 * h + 1) * (0.5f / HH));
        float sp, cp;
        sincosf(po, &sp, &cp);
        float dx = (float)(k % KX - 1) * scale;
        float dy = (float)(k / KX - 1) * scale;
        float alpha = fmaf(cp, dy, sp);   // sp + cp*dy
        float gamma = fmaf(-sp, dy, cp);  // cp - sp*dy
        float r = sqrtf(fmaf(alpha, alpha, dx * dx));
        float pol = fast_atan2f(r, gamma);
        float phi = fast_atan2f(dx, alpha);
        float gy = pol * gy_scale - 0.5f;
        int iy0 = __float2int_rd(gy);
        float fy = gy - (float)iy0;
        int iy1 = min(iy0 + 1, HH - 1);
        iy0 = max(iy0, 0);
        float4 m;
        m.x = phi * gx_scale;
        m.y = fy;
        m.z = __int_as_float(iy0 * WW);
        m.w = __int_as_float(iy1 * WW);
        s_map[ty][k] = m;
    }
    __syncthreads();

    int lane = threadIdx.x;
    int blockw = blockIdx.x * 32;
    int w = blockw + lane;
    int h = blockIdx.y * 8 + threadIdx.y;
    int ty = threadIdx.y;

    unsigned long long a0[4] = {0ull, 0ull, 0ull, 0ull};
    unsigned long long a1[4] = {0ull, 0ull, 0ull, 0ull};

    const ulonglong2* wsp = reinterpret_cast<const ulonglong2*>(ws);

#pragma unroll
    for (int k = 0; k < KK; k++) {
        float4 m = s_map[ty][k];
        int mxi = __float2int_rd(m.x);     // warp-uniform
        float fx = m.x - (float)mxi;       // warp-uniform fractional x
        int base = blockw + mxi;
        int i0 = (base + lane) & (WW - 1);
        int ie = (base + 32) & (WW - 1);   // 33rd pixel, uniform broadcast
        int y0 = __float_as_int(m.z);
        int y1 = __float_as_int(m.w);
        float fy = m.y;

        __half2 wy0 = __float2half2_rn(1.0f - fy);
        __half2 wy1 = __float2half2_rn(fy);
        __half2 wx0 = __float2half2_rn(1.0f - fx);
        __half2 wx1 = __float2half2_rn(fx);

        // batch 0
        uint4 P0 = g_h[y0 + i0];
        uint4 P1 = g_h[y1 + i0];
        uint4 E0 = g_h[y0 + ie];
        uint4 E1 = g_h[y1 + ie];
        float v0[8];
        sample8(P0, P1, E0, E1, wy0, wy1, wx0, wx1, lane, v0);

        // batch 1
        uint4 Q0 = g_h[HW + y0 + i0];
        uint4 Q1 = g_h[HW + y1 + i0];
        uint4 F0 = g_h[HW + y0 + ie];
        uint4 F1 = g_h[HW + y1 + ie];
        float v1[8];
        sample8(Q0, Q1, F0, F1, wy0, wy1, wx0, wx1, lane, v1);

        const ulonglong2* wk = wsp + k * 16;
#pragma unroll
        for (int c = 0; c < CC; c++) {
            ulonglong2 wa = wk[c * 2 + 0];
            ulonglong2 wb = wk[c * 2 + 1];
            unsigned long long vd0 = dup_f32x2(v0[c]);
            unsigned long long vd1 = dup_f32x2(v1[c]);
            ffma2(a0[0], vd0, wa.x);
            ffma2(a0[1], vd0, wa.y);
            ffma2(a0[2], vd0, wb.x);
            ffma2(a0[3], vd0, wb.y);
            ffma2(a1[0], vd1, wa.x);
            ffma2(a1[1], vd1, wa.y);
            ffma2(a1[2], vd1, wb.x);
            ffma2(a1[3], vd1, wb.y);
        }
    }

#pragma unroll
    for (int j = 0; j < 4; j++) {
        float l0, h0, l1, h1;
        asm("mov.b64 {%0, %1}, %2;" : "=f"(l0), "=f"(h0) : "l"(a0[j]));
        asm("mov.b64 {%0, %1}, %2;" : "=f"(l1), "=f"(h1) : "l"(a1[j]));
        int o = 2 * j;
        out[(size_t)((0 * OC + o) * HH + h) * WW + w]     = l0 + sb[o];
        out[(size_t)((0 * OC + o + 1) * HH + h) * WW + w] = h0 + sb[o + 1];
        out[(size_t)((1 * OC + o) * HH + h) * WW + w]     = l1 + sb[o];
        out[(size_t)((1 * OC + o + 1) * HH + h) * WW + w] = h1 + sb[o + 1];
    }
}

extern "C" void kernel_launch(void* const* d_in, const int* in_sizes, int n_in,
                              void* d_out, int out_size) {
    const float* x = (const float*)d_in[0];
    const float* wgt = (const float*)d_in[1];
    const float* bias = (const float*)d_in[2];
    float* out = (float*)d_out;

    int npix = BB * HW;
    transpose_h<<<(npix + 255) / 256, 256>>>(x);

    dim3 block(32, 8);
    dim3 grid(WW / 32, HH / 8);
    sconv_kernel<<<grid, block>>>(wgt, bias, out);
}